// round 3
// baseline (speedup 1.0000x reference)
#include <cuda_runtime.h>
#include <cuda_bf16.h>

#define BB      512     // batch
#define DD      256     // feature dim
#define RPB     4       // anchor rows per block
#define NT      256     // threads per block (main kernel)
#define NBLK    (BB / RPB)
#define MARGIN  0.2f

// Per-block partial loss sums (deterministic reduction in finalize).
__device__ float g_partials[NBLK];

__device__ __forceinline__ float blockReduceSum(float v, float* s_red) {
    #pragma unroll
    for (int o = 16; o > 0; o >>= 1) v += __shfl_down_sync(0xffffffffu, v, o);
    int w = threadIdx.x >> 5, l = threadIdx.x & 31;
    if (l == 0) s_red[w] = v;
    __syncthreads();
    int nw = blockDim.x >> 5;
    if (w == 0) {
        v = (l < nw) ? s_red[l] : 0.0f;
        #pragma unroll
        for (int o = 16; o > 0; o >>= 1) v += __shfl_down_sync(0xffffffffu, v, o);
    }
    return v;  // valid in thread 0
}

__global__ __launch_bounds__(NT)
void mcl_main_kernel(const float* __restrict__ F, const int* __restrict__ labels) {
    __shared__ int   s_lab[BB];
    __shared__ float s_fi[RPB][DD];
    __shared__ float s_sim[RPB][BB];
    __shared__ float s_pos[BB];
    __shared__ float s_neg[BB];
    __shared__ int   s_cnt[2];
    __shared__ float s_red[NT / 32];

    const int t  = threadIdx.x;
    const int i0 = blockIdx.x * RPB;

    // Load labels + the 4 anchor feature rows into smem (coalesced).
    for (int j = t; j < BB; j += NT) s_lab[j] = labels[j];
    for (int j = t; j < RPB * DD; j += NT)
        s_fi[j / DD][j % DD] = F[(i0 + j / DD) * DD + (j % DD)];
    __syncthreads();

    // sim[i0+r][k] for all k; each thread handles 2 k-values, 4 anchors each.
    for (int k = t; k < BB; k += NT) {
        const float4* fk = reinterpret_cast<const float4*>(F + (size_t)k * DD);
        float a0 = 0.f, a1 = 0.f, a2 = 0.f, a3 = 0.f;
        #pragma unroll 8
        for (int d4 = 0; d4 < DD / 4; d4++) {
            float4 v  = __ldg(fk + d4);
            float4 f0 = *reinterpret_cast<const float4*>(&s_fi[0][d4 * 4]);
            float4 f1 = *reinterpret_cast<const float4*>(&s_fi[1][d4 * 4]);
            float4 f2 = *reinterpret_cast<const float4*>(&s_fi[2][d4 * 4]);
            float4 f3 = *reinterpret_cast<const float4*>(&s_fi[3][d4 * 4]);
            a0 += v.x * f0.x + v.y * f0.y + v.z * f0.z + v.w * f0.w;
            a1 += v.x * f1.x + v.y * f1.y + v.z * f1.z + v.w * f1.w;
            a2 += v.x * f2.x + v.y * f2.y + v.z * f2.z + v.w * f2.w;
            a3 += v.x * f3.x + v.y * f3.y + v.z * f3.z + v.w * f3.w;
        }
        s_sim[0][k] = a0; s_sim[1][k] = a1; s_sim[2][k] = a2; s_sim[3][k] = a3;
    }
    __syncthreads();

    // Per anchor row: compact pos/neg sims, then pairwise hinge sum.
    float loss_acc = 0.0f;
    #pragma unroll 1
    for (int r = 0; r < RPB; r++) {
        const int i  = i0 + r;
        const int li = s_lab[i];
        if (t == 0) { s_cnt[0] = 0; s_cnt[1] = 0; }
        __syncthreads();
        for (int k = t; k < BB; k += NT) {
            if (k == i) continue;
            float v = s_sim[r][k];
            if (s_lab[k] == li) { int idx = atomicAdd(&s_cnt[0], 1); s_pos[idx] = v; }
            else               { int idx = atomicAdd(&s_cnt[1], 1); s_neg[idx] = v; }
        }
        __syncthreads();
        const int P = s_cnt[0], N = s_cnt[1];
        float acc = 0.0f;
        for (int p = 0; p < P; p++) {
            const float pm = MARGIN - s_pos[p];
            for (int n = t; n < N; n += NT)
                acc += fmaxf(0.0f, s_neg[n] + pm);
        }
        loss_acc += acc;
        __syncthreads();  // protect s_pos/s_neg/s_cnt reuse next iteration
    }

    float total = blockReduceSum(loss_acc, s_red);
    if (t == 0) g_partials[blockIdx.x] = total;
}

__global__ __launch_bounds__(BB)
void mcl_finalize_kernel(const int* __restrict__ labels, float* __restrict__ out) {
    __shared__ int   s_lab[BB];
    __shared__ float s_red[BB / 32];
    __shared__ float s_last[2];   // pos_cnt[B-1], neg_cnt[B-1]
    __shared__ float s_nv;        // num_valid
    const int t = threadIdx.x;

    s_lab[t] = labels[t];
    __syncthreads();

    // count label matches for row t
    const int li = s_lab[t];
    int cnt = 0;
    #pragma unroll 8
    for (int j = 0; j < BB; j++) cnt += (s_lab[j] == li) ? 1 : 0;
    const int posc = cnt - 1;
    const int negc = BB - cnt;
    const float valid = (posc > 0 && negc > 0) ? 1.0f : 0.0f;
    if (t == BB - 1) { s_last[0] = (float)posc; s_last[1] = (float)negc; }

    float nv = blockReduceSum(valid, s_red);
    if (t == 0) s_nv = nv;
    __syncthreads();

    // deterministic sum of block partials
    float part = (t < NBLK) ? g_partials[t] : 0.0f;
    float loss_sum = blockReduceSum(part, s_red);

    if (t == 0) {
        float denom = s_nv * s_last[0] * s_last[1];
        out[0] = (denom > 0.0f) ? (loss_sum / denom) : 0.0f;
    }
}

extern "C" void kernel_launch(void* const* d_in, const int* in_sizes, int n_in,
                              void* d_out, int out_size) {
    const float* F      = (const float*)d_in[0];
    const int*   labels = (const int*)d_in[1];
    float*       out    = (float*)d_out;
    (void)in_sizes; (void)n_in; (void)out_size;

    mcl_main_kernel<<<NBLK, NT>>>(F, labels);
    mcl_finalize_kernel<<<1, BB>>>(labels, out);
}

// round 5
// speedup vs baseline: 2.1578x; 2.1578x over previous
#include <cuda_runtime.h>
#include <cuda_bf16.h>

#define BB      512     // batch
#define DD      256     // feature dim
#define RPB     4       // anchor rows per block
#define NT      256     // threads per block (main kernel)
#define NBLK    (BB / RPB)   // 128
#define MARGIN  0.2f

// Transposed features FT[d][k] (512 KB) — enables coalesced k-major reads.
__device__ float g_FT[DD * BB];
// Per-block partial loss sums + completion counter for fused finalize.
__device__ float g_partials[NBLK];
__device__ unsigned int g_done;   // zero-init; last block resets to 0 each launch

__device__ __forceinline__ float blockReduceSum(float v, float* s_red) {
    #pragma unroll
    for (int o = 16; o > 0; o >>= 1) v += __shfl_down_sync(0xffffffffu, v, o);
    __syncthreads();                       // safe back-to-back reuse of s_red
    int w = threadIdx.x >> 5, l = threadIdx.x & 31;
    if (l == 0) s_red[w] = v;
    __syncthreads();
    int nw = blockDim.x >> 5;
    if (w == 0) {
        v = (l < nw) ? s_red[l] : 0.0f;
        #pragma unroll
        for (int o = 16; o > 0; o >>= 1) v += __shfl_down_sync(0xffffffffu, v, o);
    }
    return v;  // valid in thread 0
}

// ---------------------------------------------------------------------------
// Kernel 0: 32x32 tiled transpose  F[512][256] -> FT[256][512]
// ---------------------------------------------------------------------------
__global__ __launch_bounds__(256)
void mcl_transpose_kernel(const float* __restrict__ F) {
    __shared__ float tile[32][33];
    const int d0 = blockIdx.x * 32;   // d-tile
    const int k0 = blockIdx.y * 32;   // k-tile
    #pragma unroll
    for (int j = 0; j < 32; j += 8)
        tile[threadIdx.y + j][threadIdx.x] =
            F[(size_t)(k0 + threadIdx.y + j) * DD + (d0 + threadIdx.x)];
    __syncthreads();
    #pragma unroll
    for (int j = 0; j < 32; j += 8)
        g_FT[(size_t)(d0 + threadIdx.y + j) * BB + (k0 + threadIdx.x)] =
            tile[threadIdx.x][threadIdx.y + j];
}

// ---------------------------------------------------------------------------
// Kernel 1: sim + hinge pairs + fused finalize (last block)
// ---------------------------------------------------------------------------
__global__ __launch_bounds__(NT)
void mcl_main_kernel(const float* __restrict__ F, const int* __restrict__ labels,
                     float* __restrict__ out) {
    __shared__ int    s_lab[BB];
    __shared__ float4 s_fit[DD];          // [d] -> (anchor0..anchor3) value, 4KB
    __shared__ float  s_sim[RPB][BB];     // 8KB
    __shared__ float4 s_half[NT / 2 * 4]; // d-half partials: [tq*4 + r], 8KB
    __shared__ float4 s_pos4[132];        // padded positives (516 floats)
    __shared__ float  s_neg[BB];
    __shared__ int    s_cnt[2];
    __shared__ float  s_red[NT / 32];
    __shared__ int    s_hist[16];
    __shared__ int    s_isLast;

    const int t  = threadIdx.x;
    const int i0 = blockIdx.x * RPB;
    float* s_pos = reinterpret_cast<float*>(s_pos4);

    // Labels + anchor features (transposed into smem: s_fit[d] = {F[i0+r][d]}).
    for (int j = t; j < BB; j += NT) s_lab[j] = labels[j];
    for (int j = t; j < DD; j += NT) {
        float4 v;
        v.x = F[(size_t)(i0 + 0) * DD + j];
        v.y = F[(size_t)(i0 + 1) * DD + j];
        v.z = F[(size_t)(i0 + 2) * DD + j];
        v.w = F[(size_t)(i0 + 3) * DD + j];
        s_fit[j] = v;
    }
    __syncthreads();

    // --- sim phase: coalesced FT reads. Thread covers k-quad tq over d-half h.
    const int tq = t & 127;       // quad id: k = 4*tq .. 4*tq+3
    const int h  = t >> 7;        // d-half: [h*128, h*128+128)
    float4 acc[RPB];
    #pragma unroll
    for (int r = 0; r < RPB; r++) acc[r] = make_float4(0.f, 0.f, 0.f, 0.f);

    const float4* ftp = reinterpret_cast<const float4*>(g_FT) + tq + (size_t)(h * 128) * (BB / 4);
    #pragma unroll 8
    for (int d = 0; d < DD / 2; d++) {
        float4 kv = ftp[(size_t)d * (BB / 4)];
        float4 fv = s_fit[h * 128 + d];
        acc[0].x += kv.x * fv.x; acc[0].y += kv.y * fv.x; acc[0].z += kv.z * fv.x; acc[0].w += kv.w * fv.x;
        acc[1].x += kv.x * fv.y; acc[1].y += kv.y * fv.y; acc[1].z += kv.z * fv.y; acc[1].w += kv.w * fv.y;
        acc[2].x += kv.x * fv.z; acc[2].y += kv.y * fv.z; acc[2].z += kv.z * fv.z; acc[2].w += kv.w * fv.z;
        acc[3].x += kv.x * fv.w; acc[3].y += kv.y * fv.w; acc[3].z += kv.z * fv.w; acc[3].w += kv.w * fv.w;
    }
    if (h == 1) {
        #pragma unroll
        for (int r = 0; r < RPB; r++) s_half[tq * 4 + r] = acc[r];
    }
    __syncthreads();
    if (h == 0) {
        #pragma unroll
        for (int r = 0; r < RPB; r++) {
            float4 o = s_half[tq * 4 + r];
            s_sim[r][4 * tq + 0] = acc[r].x + o.x;
            s_sim[r][4 * tq + 1] = acc[r].y + o.y;
            s_sim[r][4 * tq + 2] = acc[r].z + o.z;
            s_sim[r][4 * tq + 3] = acc[r].w + o.w;
        }
    }
    __syncthreads();

    // --- pair phase per anchor row ---
    float loss_acc = 0.0f;
    #pragma unroll 1
    for (int r = 0; r < RPB; r++) {
        const int i  = i0 + r;
        const int li = s_lab[i];
        if (t == 0) { s_cnt[0] = 0; s_cnt[1] = 0; }
        __syncthreads();
        for (int k = t; k < BB; k += NT) {
            if (k == i) continue;
            float v = s_sim[r][k];
            if (s_lab[k] == li) { int idx = atomicAdd(&s_cnt[0], 1); s_pos[idx] = v; }
            else               { int idx = atomicAdd(&s_cnt[1], 1); s_neg[idx] = v; }
        }
        __syncthreads();
        const int P = s_cnt[0], N = s_cnt[1];
        if (t < 4) s_pos[P + t] = 1e30f;          // pad to multiple of 4
        __syncthreads();

        const float t0 = (t      < N) ? (MARGIN + s_neg[t])      : -1e30f;
        const float t1 = (t + NT < N) ? (MARGIN + s_neg[t + NT]) : -1e30f;
        float a0 = 0.f, a1 = 0.f;
        const int P4 = (P + 3) >> 2;
        for (int pc = 0; pc < P4; pc++) {
            float4 pv = s_pos4[pc];
            float s0 = fmaxf(0.f, t0 - pv.x) + fmaxf(0.f, t0 - pv.y);
            float s1 = fmaxf(0.f, t0 - pv.z) + fmaxf(0.f, t0 - pv.w);
            float s2 = fmaxf(0.f, t1 - pv.x) + fmaxf(0.f, t1 - pv.y);
            float s3 = fmaxf(0.f, t1 - pv.z) + fmaxf(0.f, t1 - pv.w);
            a0 += s0 + s1;
            a1 += s2 + s3;
        }
        loss_acc += a0 + a1;
        __syncthreads();  // protect s_pos/s_neg/s_cnt reuse
    }

    // --- block partial + fused finalize in last-finishing block ---
    float total = blockReduceSum(loss_acc, s_red);
    if (t == 0) {
        g_partials[blockIdx.x] = total;
        __threadfence();
        unsigned v = atomicAdd(&g_done, 1u);
        s_isLast = (v == NBLK - 1) ? 1 : 0;
    }
    __syncthreads();
    if (s_isLast) {
        __threadfence();
        float part = (t < NBLK) ? g_partials[t] : 0.0f;
        float loss_sum = blockReduceSum(part, s_red);

        if (t < 16) s_hist[t] = 0;
        __syncthreads();
        for (int k = t; k < BB; k += NT) atomicAdd(&s_hist[s_lab[k]], 1);
        __syncthreads();

        if (t == 0) {
            float nv = 0.0f;
            #pragma unroll
            for (int c = 0; c < 16; c++) {
                int hc = s_hist[c];
                if (hc >= 2 && hc < BB) nv += (float)hc;  // posc>0 && negc>0
            }
            int cl = s_lab[BB - 1];
            float pcl = (float)(s_hist[cl] - 1);
            float ncl = (float)(BB - s_hist[cl]);
            float denom = nv * pcl * ncl;
            out[0] = (denom > 0.0f) ? (loss_sum / denom) : 0.0f;
            g_done = 0;  // reset for next graph replay
        }
    }
}

extern "C" void kernel_launch(void* const* d_in, const int* in_sizes, int n_in,
                              void* d_out, int out_size) {
    const float* F      = (const float*)d_in[0];
    const int*   labels = (const int*)d_in[1];
    float*       out    = (float*)d_out;
    (void)in_sizes; (void)n_in; (void)out_size;

    mcl_transpose_kernel<<<dim3(DD / 32, BB / 32), dim3(32, 8)>>>(F);
    mcl_main_kernel<<<NBLK, NT>>>(F, labels, out);
}

// round 6
// speedup vs baseline: 3.3563x; 1.5554x over previous
#include <cuda_runtime.h>
#include <cuda_bf16.h>

#define BB      512     // batch
#define DD      256     // feature dim
#define NTILE   16      // 512/32 tiles per side
#define NTRI    136     // NTILE*(NTILE+1)/2 upper-triangular tiles
#define MARGIN  0.2f

__device__ float g_sim[BB * BB];        // 1 MB similarity matrix
__device__ float g_partials[BB];        // per-anchor-row partial loss
__device__ unsigned int g_done;         // zero-init; reset by last block

__device__ __forceinline__ float blockReduceSum(float v, float* s_red) {
    #pragma unroll
    for (int o = 16; o > 0; o >>= 1) v += __shfl_down_sync(0xffffffffu, v, o);
    __syncthreads();
    int w = threadIdx.x >> 5, l = threadIdx.x & 31;
    if (l == 0) s_red[w] = v;
    __syncthreads();
    int nw = blockDim.x >> 5;
    if (w == 0) {
        v = (l < nw) ? s_red[l] : 0.0f;
        #pragma unroll
        for (int o = 16; o > 0; o >>= 1) v += __shfl_down_sync(0xffffffffu, v, o);
    }
    return v;  // valid in thread 0
}

// ---------------------------------------------------------------------------
// Kernel 0: symmetric tiled SYRK  sim = F F^T (upper tiles computed, mirrored)
// 32x32 output tiles, 256 threads, 2x2 register blocking, dd-major smem.
// ---------------------------------------------------------------------------
__global__ __launch_bounds__(256)
void mcl_gemm_kernel(const float* __restrict__ F) {
    __shared__ float AsT[32][34];   // [dd][row], 34-stride keeps float2 aligned
    __shared__ float BsT[32][34];

    const int t  = threadIdx.x;
    const int tx = t & 15, ty = t >> 4;

    // decode triangular tile index (bi <= bk)
    int bi = 0, rem = blockIdx.x;
    while (rem >= NTILE - bi) { rem -= NTILE - bi; bi++; }
    const int bk = bi + rem;
    const int i0 = bi * 32, k0 = bk * 32;

    float c00 = 0.f, c01 = 0.f, c10 = 0.f, c11 = 0.f;

    for (int d0 = 0; d0 < DD; d0 += 32) {
        #pragma unroll
        for (int j = 0; j < 4; j++) {
            int idx = t + j * 256;
            int r = idx >> 5, c = idx & 31;
            AsT[c][r] = F[(size_t)(i0 + r) * DD + d0 + c];
            BsT[c][r] = F[(size_t)(k0 + r) * DD + d0 + c];
        }
        __syncthreads();
        #pragma unroll
        for (int dd = 0; dd < 32; dd++) {
            float2 a  = *reinterpret_cast<float2*>(&AsT[dd][2 * ty]);
            float2 bv = *reinterpret_cast<float2*>(&BsT[dd][2 * tx]);
            c00 += a.x * bv.x; c01 += a.x * bv.y;
            c10 += a.y * bv.x; c11 += a.y * bv.y;
        }
        __syncthreads();
    }

    float* C = g_sim;
    *reinterpret_cast<float2*>(&C[(size_t)(i0 + 2 * ty)     * BB + k0 + 2 * tx]) = make_float2(c00, c01);
    *reinterpret_cast<float2*>(&C[(size_t)(i0 + 2 * ty + 1) * BB + k0 + 2 * tx]) = make_float2(c10, c11);
    if (bi != bk) {  // mirror tile
        *reinterpret_cast<float2*>(&C[(size_t)(k0 + 2 * tx)     * BB + i0 + 2 * ty]) = make_float2(c00, c10);
        *reinterpret_cast<float2*>(&C[(size_t)(k0 + 2 * tx + 1) * BB + i0 + 2 * ty]) = make_float2(c01, c11);
    }
}

// ---------------------------------------------------------------------------
// Kernel 1: one block per anchor row: compact pos/neg, hinge-pair sum,
//           fused finalize in the last-finishing block.
// ---------------------------------------------------------------------------
__global__ __launch_bounds__(256)
void mcl_pair_kernel(const int* __restrict__ labels, float* __restrict__ out) {
    __shared__ int    s_lab[BB];
    __shared__ float4 s_pos4[132];     // 516 floats, padded positives
    __shared__ float  s_neg[BB];
    __shared__ int    s_cnt[2];
    __shared__ float  s_red[8];
    __shared__ int    s_hist[16];
    __shared__ int    s_isLast;

    const int t = threadIdx.x;
    const int i = blockIdx.x;
    float* s_pos = reinterpret_cast<float*>(s_pos4);

    s_lab[t]       = labels[t];
    s_lab[t + 256] = labels[t + 256];
    if (t == 0) { s_cnt[0] = 0; s_cnt[1] = 0; }
    __syncthreads();

    const int li = s_lab[i];
    const float* simrow = g_sim + (size_t)i * BB;
    #pragma unroll
    for (int j = 0; j < 2; j++) {
        int k = t + j * 256;
        if (k == i) continue;
        float v = simrow[k];
        if (s_lab[k] == li) { int idx = atomicAdd(&s_cnt[0], 1); s_pos[idx] = v; }
        else                { int idx = atomicAdd(&s_cnt[1], 1); s_neg[idx] = v; }
    }
    __syncthreads();
    const int P = s_cnt[0], N = s_cnt[1];
    if (t < 4) s_pos[P + t] = 1e30f;     // pad to multiple of 4
    __syncthreads();

    const float t0 = (t       < N) ? (MARGIN + s_neg[t])       : -1e30f;
    const float t1 = (t + 256 < N) ? (MARGIN + s_neg[t + 256]) : -1e30f;
    float a0 = 0.f, a1 = 0.f;
    const int P4 = (P + 3) >> 2;
    for (int pc = 0; pc < P4; pc++) {
        float4 pv = s_pos4[pc];
        a0 += fmaxf(0.f, t0 - pv.x) + fmaxf(0.f, t0 - pv.y)
            + fmaxf(0.f, t0 - pv.z) + fmaxf(0.f, t0 - pv.w);
        a1 += fmaxf(0.f, t1 - pv.x) + fmaxf(0.f, t1 - pv.y)
            + fmaxf(0.f, t1 - pv.z) + fmaxf(0.f, t1 - pv.w);
    }

    float total = blockReduceSum(a0 + a1, s_red);
    if (t == 0) {
        g_partials[i] = total;
        __threadfence();
        unsigned v = atomicAdd(&g_done, 1u);
        s_isLast = (v == BB - 1) ? 1 : 0;
    }
    __syncthreads();

    if (s_isLast) {
        __threadfence();
        float part = g_partials[t] + g_partials[t + 256];
        float loss_sum = blockReduceSum(part, s_red);

        if (t < 16) s_hist[t] = 0;
        __syncthreads();
        atomicAdd(&s_hist[s_lab[t]], 1);
        atomicAdd(&s_hist[s_lab[t + 256]], 1);
        __syncthreads();

        if (t == 0) {
            float nv = 0.0f;
            #pragma unroll
            for (int c = 0; c < 16; c++) {
                int hc = s_hist[c];
                if (hc >= 2 && hc < BB) nv += (float)hc;   // posc>0 && negc>0
            }
            int   cl    = s_lab[BB - 1];
            float pcl   = (float)(s_hist[cl] - 1);
            float ncl   = (float)(BB - s_hist[cl]);
            float denom = nv * pcl * ncl;
            out[0] = (denom > 0.0f) ? (loss_sum / denom) : 0.0f;
            g_done = 0;   // reset for next graph replay
        }
    }
}

extern "C" void kernel_launch(void* const* d_in, const int* in_sizes, int n_in,
                              void* d_out, int out_size) {
    const float* F      = (const float*)d_in[0];
    const int*   labels = (const int*)d_in[1];
    float*       out    = (float*)d_out;
    (void)in_sizes; (void)n_in; (void)out_size;

    mcl_gemm_kernel<<<NTRI, 256>>>(F);
    mcl_pair_kernel<<<BB, 256>>>(labels, out);
}

// round 9
// speedup vs baseline: 4.2462x; 1.2652x over previous
#include <cuda_runtime.h>
#include <cuda_bf16.h>

#define BB      512     // batch
#define DD      256     // feature dim
#define NTILE   16      // 512/32 tiles per side
#define NTRI    136     // NTILE*(NTILE+1)/2 upper-triangular tiles
#define MARGIN  0.2f

__device__ float g_simH[2][BB * BB];    // D-split partial sims (2 MB)
__device__ float g_partials[BB];        // per-anchor-row partial loss
__device__ unsigned int g_done;         // zero-init; reset by last block

__device__ __forceinline__ float blockReduceSum(float v, float* s_red) {
    #pragma unroll
    for (int o = 16; o > 0; o >>= 1) v += __shfl_down_sync(0xffffffffu, v, o);
    __syncthreads();
    int w = threadIdx.x >> 5, l = threadIdx.x & 31;
    if (l == 0) s_red[w] = v;
    __syncthreads();
    int nw = blockDim.x >> 5;
    if (w == 0) {
        v = (l < nw) ? s_red[l] : 0.0f;
        #pragma unroll
        for (int o = 16; o > 0; o >>= 1) v += __shfl_down_sync(0xffffffffu, v, o);
    }
    return v;  // valid in thread 0
}

// ---------------------------------------------------------------------------
// Kernel 0: D-split symmetric SYRK. blockIdx.x = tri*2 + half.
// Each block: 32x32 tile over D-half of 128, double-buffered via reg prefetch.
// ---------------------------------------------------------------------------
__global__ __launch_bounds__(256)
void mcl_gemm_kernel(const float* __restrict__ F) {
    __shared__ float AsT[32][34];   // [dd][row]
    __shared__ float BsT[32][34];

    const int t    = threadIdx.x;
    const int tx   = t & 15, ty = t >> 4;
    const int half = blockIdx.x & 1;
    int bi = 0, rem = blockIdx.x >> 1;
    while (rem >= NTILE - bi) { rem -= NTILE - bi; bi++; }
    const int bk = bi + rem;
    const int i0 = bi * 32, k0 = bk * 32;

    const int lr = t >> 5;          // ld row group base (x8 rows via j)
    const int lc = t & 31;          // ld col (dd within chunk)
    const int dbase = half * 128;

    float c00 = 0.f, c01 = 0.f, c10 = 0.f, c11 = 0.f;
    float rA[4], rB[4];

    // prefetch chunk 0
    #pragma unroll
    for (int j = 0; j < 4; j++) {
        rA[j] = F[(size_t)(i0 + lr + j * 8) * DD + dbase + lc];
        rB[j] = F[(size_t)(k0 + lr + j * 8) * DD + dbase + lc];
    }

    #pragma unroll
    for (int c = 0; c < 4; c++) {
        #pragma unroll
        for (int j = 0; j < 4; j++) {
            AsT[lc][lr + j * 8] = rA[j];
            BsT[lc][lr + j * 8] = rB[j];
        }
        __syncthreads();
        if (c < 3) {
            const int dn = dbase + (c + 1) * 32;
            #pragma unroll
            for (int j = 0; j < 4; j++) {
                rA[j] = F[(size_t)(i0 + lr + j * 8) * DD + dn + lc];
                rB[j] = F[(size_t)(k0 + lr + j * 8) * DD + dn + lc];
            }
        }
        #pragma unroll
        for (int dd = 0; dd < 32; dd++) {
            float2 a  = *reinterpret_cast<float2*>(&AsT[dd][2 * ty]);
            float2 bv = *reinterpret_cast<float2*>(&BsT[dd][2 * tx]);
            c00 += a.x * bv.x; c01 += a.x * bv.y;
            c10 += a.y * bv.x; c11 += a.y * bv.y;
        }
        __syncthreads();
    }

    float* C = g_simH[half];
    *reinterpret_cast<float2*>(&C[(size_t)(i0 + 2 * ty)     * BB + k0 + 2 * tx]) = make_float2(c00, c01);
    *reinterpret_cast<float2*>(&C[(size_t)(i0 + 2 * ty + 1) * BB + k0 + 2 * tx]) = make_float2(c10, c11);
    if (bi != bk) {
        *reinterpret_cast<float2*>(&C[(size_t)(k0 + 2 * tx)     * BB + i0 + 2 * ty]) = make_float2(c00, c10);
        *reinterpret_cast<float2*>(&C[(size_t)(k0 + 2 * tx + 1) * BB + i0 + 2 * ty]) = make_float2(c01, c11);
    }
}

// ---------------------------------------------------------------------------
// Kernel 1: one block per anchor row; atomic-free ballot compaction,
//           hinge-pair sum, fused finalize in the last-finishing block.
// 256 threads = 8 warps; warp w owns k-chunk A (slot w) and B (slot 8+w).
// ---------------------------------------------------------------------------
__global__ __launch_bounds__(256)
void mcl_pair_kernel(const int* __restrict__ labels, float* __restrict__ out) {
    __shared__ int    s_lab[BB];
    __shared__ float4 s_pos4[132];     // 528 floats, padded positives
    __shared__ float  s_neg[BB];
    __shared__ int    s_pcnt[32], s_ncnt[32];
    __shared__ int    s_poff[32], s_noff[32];
    __shared__ int    s_cnt[2];
    __shared__ float  s_red[8];
    __shared__ int    s_hist[16];
    __shared__ int    s_isLast;

    const int t    = threadIdx.x;
    const int i    = blockIdx.x;
    const int lane = t & 31;
    const int w    = t >> 5;           // 0..7
    float* s_pos = reinterpret_cast<float*>(s_pos4);

    s_lab[t]       = labels[t];
    s_lab[t + 256] = labels[t + 256];
    if (t < 32) { s_pcnt[t] = 0; s_ncnt[t] = 0; }   // zero ALL scan slots
    __syncthreads();

    const int li = s_lab[i];
    const float* rA = g_simH[0] + (size_t)i * BB;
    const float* rB = g_simH[1] + (size_t)i * BB;
    const int kA = t, kB = t + 256;
    const float vA = rA[kA] + rB[kA];
    const float vB = rA[kB] + rB[kB];
    const bool eqA = (s_lab[kA] == li), eqB = (s_lab[kB] == li);
    const bool pA = (kA != i) && eqA, nA = (kA != i) && !eqA;
    const bool pB = (kB != i) && eqB, nB = (kB != i) && !eqB;
    const unsigned bpA = __ballot_sync(0xffffffffu, pA);
    const unsigned bnA = __ballot_sync(0xffffffffu, nA);
    const unsigned bpB = __ballot_sync(0xffffffffu, pB);
    const unsigned bnB = __ballot_sync(0xffffffffu, nB);
    if (lane == 0) {
        s_pcnt[w] = __popc(bpA); s_pcnt[8 + w] = __popc(bpB);
        s_ncnt[w] = __popc(bnA); s_ncnt[8 + w] = __popc(bnB);
    }
    __syncthreads();
    if (w == 0) {                       // exclusive scan of pos counts (16 live)
        int c = s_pcnt[lane], x = c;
        #pragma unroll
        for (int o = 1; o < 32; o <<= 1) {
            int y = __shfl_up_sync(0xffffffffu, x, o);
            if (lane >= o) x += y;
        }
        s_poff[lane] = x - c;
        if (lane == 31) s_cnt[0] = x;
    } else if (w == 1) {                // exclusive scan of neg counts
        int c = s_ncnt[lane], x = c;
        #pragma unroll
        for (int o = 1; o < 32; o <<= 1) {
            int y = __shfl_up_sync(0xffffffffu, x, o);
            if (lane >= o) x += y;
        }
        s_noff[lane] = x - c;
        if (lane == 31) s_cnt[1] = x;
    }
    __syncthreads();
    const unsigned lt = (1u << lane) - 1u;
    if (pA) s_pos[s_poff[w]     + __popc(bpA & lt)] = vA;
    if (pB) s_pos[s_poff[8 + w] + __popc(bpB & lt)] = vB;
    if (nA) s_neg[s_noff[w]     + __popc(bnA & lt)] = vA;
    if (nB) s_neg[s_noff[8 + w] + __popc(bnB & lt)] = vB;
    __syncthreads();

    const int P = s_cnt[0], N = s_cnt[1];
    if (t < 4) s_pos[P + t] = 1e30f;    // pad to multiple of 4 (max idx 514 < 528)
    __syncthreads();

    const float t0 = (t       < N) ? (MARGIN + s_neg[t])       : -1e30f;
    const float t1 = (t + 256 < N) ? (MARGIN + s_neg[t + 256]) : -1e30f;
    float a0 = 0.f, a1 = 0.f;
    const int P4 = (P + 3) >> 2;
    for (int pc = 0; pc < P4; pc++) {
        float4 pv = s_pos4[pc];
        a0 += fmaxf(0.f, t0 - pv.x) + fmaxf(0.f, t0 - pv.y)
            + fmaxf(0.f, t0 - pv.z) + fmaxf(0.f, t0 - pv.w);
        a1 += fmaxf(0.f, t1 - pv.x) + fmaxf(0.f, t1 - pv.y)
            + fmaxf(0.f, t1 - pv.z) + fmaxf(0.f, t1 - pv.w);
    }

    float total = blockReduceSum(a0 + a1, s_red);
    if (t == 0) {
        g_partials[i] = total;
        __threadfence();
        unsigned v = atomicAdd(&g_done, 1u);
        s_isLast = (v == BB - 1) ? 1 : 0;
    }
    __syncthreads();

    if (s_isLast) {
        __threadfence();
        float part = g_partials[t] + g_partials[t + 256];
        float loss_sum = blockReduceSum(part, s_red);

        if (t < 16) s_hist[t] = 0;
        __syncthreads();
        atomicAdd(&s_hist[s_lab[t]], 1);
        atomicAdd(&s_hist[s_lab[t + 256]], 1);
        __syncthreads();

        if (t == 0) {
            float nv = 0.0f;
            #pragma unroll
            for (int c = 0; c < 16; c++) {
                int hc = s_hist[c];
                if (hc >= 2 && hc < BB) nv += (float)hc;   // posc>0 && negc>0
            }
            int   cl    = s_lab[BB - 1];
            float pcl   = (float)(s_hist[cl] - 1);
            float ncl   = (float)(BB - s_hist[cl]);
            float denom = nv * pcl * ncl;
            out[0] = (denom > 0.0f) ? (loss_sum / denom) : 0.0f;
            g_done = 0;   // reset for next graph replay
        }
    }
}

extern "C" void kernel_launch(void* const* d_in, const int* in_sizes, int n_in,
                              void* d_out, int out_size) {
    const float* F      = (const float*)d_in[0];
    const int*   labels = (const int*)d_in[1];
    float*       out    = (float*)d_out;
    (void)in_sizes; (void)n_in; (void)out_size;

    mcl_gemm_kernel<<<NTRI * 2, 256>>>(F);
    mcl_pair_kernel<<<BB, 256>>>(labels, out);
}